// round 11
// baseline (speedup 1.0000x reference)
#include <cuda_runtime.h>

#define T_DIM 3
#define B_DIM 100000
#define D_DIM 128
#define NEG_SLOPE 0.01f
#define TOTAL_ROWS (T_DIM * B_DIM)

// One warp per PAIR of consecutive (t,b) rows, one-shot grid. 1024-thread CTAs
// (32 warps) widen the per-CTA contiguous DRAM window per stream to 32KB for
// maximal row-buffer locality; regs=56 so 1 CTA/SM keeps the same ~32 warps/SM.
// Streaming (.cs) on all zero-reuse tensors; fast-approx softmax reciprocal.
__global__ __launch_bounds__(1024, 1)
void attconv_kernel(const float4* __restrict__ h_center,   // (T*B*32) float4
                    const float4* __restrict__ h_neigh,    // (T*T*B*32) float4
                    const float4* __restrict__ att_w,      // (T*64) float4
                    const float*  __restrict__ att_b,      // (T)
                    float4* __restrict__ out)              // (T*B*32) float4
{
    const int gwarp = (blockIdx.x * blockDim.x + threadIdx.x) >> 5;
    const int lane  = threadIdx.x & 31;
    const int row0  = gwarp * 2;                 // first row of the pair
    if (row0 >= TOTAL_ROWS) return;

    const int t  = row0 / B_DIM;                 // same t for both rows
    const int b0 = row0 - t * B_DIM;

    const int ctr0 = row0 * 32 + lane;                         // row0 center
    const int nb0  = (t * T_DIM * B_DIM + b0) * 32 + lane;     // row0 neigh base

    // Issue all 12 big loads up front, streaming (zero reuse).
    const float4 ca = __ldcs(h_center + ctr0);
    const float4 cb = __ldcs(h_center + ctr0 + 32);
    const float4 a0 = __ldcs(h_neigh + nb0 + 0 * B_DIM * 32);
    const float4 b0v= __ldcs(h_neigh + nb0 + 0 * B_DIM * 32 + 32);
    const float4 a1 = __ldcs(h_neigh + nb0 + 1 * B_DIM * 32);
    const float4 b1v= __ldcs(h_neigh + nb0 + 1 * B_DIM * 32 + 32);
    const float4 a2 = __ldcs(h_neigh + nb0 + 2 * B_DIM * 32);
    const float4 b2v= __ldcs(h_neigh + nb0 + 2 * B_DIM * 32 + 32);
    const float4 wh = __ldg(att_w + t * 64 + lane);       // reused: keep cached
    const float4 we = __ldg(att_w + t * 64 + 32 + lane);
    const float bias = __ldg(att_b + t);

    // ---- row 0 partials (score_h folded in) ----
    float pha = ca.x * wh.x + ca.y * wh.y + ca.z * wh.z + ca.w * wh.w;
    float pa0 = a0.x * we.x + a0.y * we.y + a0.z * we.z + a0.w * we.w + pha;
    float pa1 = a1.x * we.x + a1.y * we.y + a1.z * we.z + a1.w * we.w + pha;
    float pa2 = a2.x * we.x + a2.y * we.y + a2.z * we.z + a2.w * we.w + pha;
    float pa3 = ca.x * we.x + ca.y * we.y + ca.z * we.z + ca.w * we.w + pha;
    // ---- row 1 partials ----
    float phb = cb.x * wh.x + cb.y * wh.y + cb.z * wh.z + cb.w * wh.w;
    float pb0 = b0v.x * we.x + b0v.y * we.y + b0v.z * we.z + b0v.w * we.w + phb;
    float pb1 = b1v.x * we.x + b1v.y * we.y + b1v.z * we.z + b1v.w * we.w + phb;
    float pb2 = b2v.x * we.x + b2v.y * we.y + b2v.z * we.z + b2v.w * we.w + phb;
    float pb3 = cb.x * we.x + cb.y * we.y + cb.z * we.z + cb.w * we.w + phb;

    // 8 butterfly reductions, interleaved for ILP.
    #pragma unroll
    for (int off = 16; off > 0; off >>= 1) {
        pa0 += __shfl_xor_sync(0xFFFFFFFFu, pa0, off);
        pa1 += __shfl_xor_sync(0xFFFFFFFFu, pa1, off);
        pa2 += __shfl_xor_sync(0xFFFFFFFFu, pa2, off);
        pa3 += __shfl_xor_sync(0xFFFFFFFFu, pa3, off);
        pb0 += __shfl_xor_sync(0xFFFFFFFFu, pb0, off);
        pb1 += __shfl_xor_sync(0xFFFFFFFFu, pb1, off);
        pb2 += __shfl_xor_sync(0xFFFFFFFFu, pb2, off);
        pb3 += __shfl_xor_sync(0xFFFFFFFFu, pb3, off);
    }

    // ---- row 0 softmax + output ----
    {
        float s0 = pa0 + bias, s1 = pa1 + bias, s2 = pa2 + bias, s3 = pa3 + bias;
        s0 = (s0 >= 0.f) ? s0 : NEG_SLOPE * s0;
        s1 = (s1 >= 0.f) ? s1 : NEG_SLOPE * s1;
        s2 = (s2 >= 0.f) ? s2 : NEG_SLOPE * s2;
        s3 = (s3 >= 0.f) ? s3 : NEG_SLOPE * s3;
        float m = fmaxf(fmaxf(s0, s1), fmaxf(s2, s3));
        float e0 = __expf(s0 - m), e1 = __expf(s1 - m);
        float e2 = __expf(s2 - m), e3 = __expf(s3 - m);
        float inv = __fdividef(1.0f, e0 + e1 + e2 + e3);
        float w0 = e0 * inv, w1 = e1 * inv, w2 = e2 * inv, w3 = e3 * inv;
        float4 o;
        o.x = w0 * a0.x + w1 * a1.x + w2 * a2.x + w3 * ca.x;
        o.y = w0 * a0.y + w1 * a1.y + w2 * a2.y + w3 * ca.y;
        o.z = w0 * a0.z + w1 * a1.z + w2 * a2.z + w3 * ca.z;
        o.w = w0 * a0.w + w1 * a1.w + w2 * a2.w + w3 * ca.w;
        __stcs(out + ctr0, o);
    }
    // ---- row 1 softmax + output ----
    {
        float s0 = pb0 + bias, s1 = pb1 + bias, s2 = pb2 + bias, s3 = pb3 + bias;
        s0 = (s0 >= 0.f) ? s0 : NEG_SLOPE * s0;
        s1 = (s1 >= 0.f) ? s1 : NEG_SLOPE * s1;
        s2 = (s2 >= 0.f) ? s2 : NEG_SLOPE * s2;
        s3 = (s3 >= 0.f) ? s3 : NEG_SLOPE * s3;
        float m = fmaxf(fmaxf(s0, s1), fmaxf(s2, s3));
        float e0 = __expf(s0 - m), e1 = __expf(s1 - m);
        float e2 = __expf(s2 - m), e3 = __expf(s3 - m);
        float inv = __fdividef(1.0f, e0 + e1 + e2 + e3);
        float w0 = e0 * inv, w1 = e1 * inv, w2 = e2 * inv, w3 = e3 * inv;
        float4 o;
        o.x = w0 * b0v.x + w1 * b1v.x + w2 * b2v.x + w3 * cb.x;
        o.y = w0 * b0v.y + w1 * b1v.y + w2 * b2v.y + w3 * cb.y;
        o.z = w0 * b0v.z + w1 * b1v.z + w2 * b2v.z + w3 * cb.z;
        o.w = w0 * b0v.w + w1 * b1v.w + w2 * b2v.w + w3 * cb.w;
        __stcs(out + ctr0 + 32, o);
    }
}

extern "C" void kernel_launch(void* const* d_in, const int* in_sizes, int n_in,
                              void* d_out, int out_size) {
    const float4* h_center = (const float4*)d_in[0];
    const float4* h_neigh  = (const float4*)d_in[1];
    const float4* att_w    = (const float4*)d_in[2];
    const float*  att_b    = (const float*)d_in[3];
    float4* out = (float4*)d_out;

    const int total_pairs = TOTAL_ROWS / 2;             // 150000 warps
    const int threads = 1024;                           // 32 warps/block
    const int blocks = (total_pairs * 32 + threads - 1) / threads;  // 4688

    attconv_kernel<<<blocks, threads>>>(h_center, h_neigh, att_w, att_b, out);
}

// round 12
// speedup vs baseline: 1.0241x; 1.0241x over previous
#include <cuda_runtime.h>

#define T_DIM 3
#define B_DIM 100000
#define D_DIM 128
#define NEG_SLOPE 0.01f
#define TOTAL_ROWS (T_DIM * B_DIM)

// FINAL (R10 config — measured optimum across all swept axes):
// - One warp per PAIR of consecutive (t,b) rows, one-shot grid (CTA churn
//   keeps the memory pipe full; persistent grid regressed).
// - 512-thread CTAs: 16KB contiguous per-CTA DRAM window per stream (256 and
//   1024 both measured slower).
// - All 12 big loads issued up front (MLP=12/warp), .cs streaming hints on
//   the zero-reuse tensors, .stcs stores.
// - score_h folded into neighbor partials (4 reductions/row), fast-approx
//   softmax reciprocal (rel_err 1e-7 vs 1e-3 budget).
// Kernel is DRAM-bound at ~88% of HBM spec (~7 TB/s); remaining gap is
// memory-controller turnaround on 5 interleaved streams.
__global__ __launch_bounds__(512, 2)
void attconv_kernel(const float4* __restrict__ h_center,   // (T*B*32) float4
                    const float4* __restrict__ h_neigh,    // (T*T*B*32) float4
                    const float4* __restrict__ att_w,      // (T*64) float4
                    const float*  __restrict__ att_b,      // (T)
                    float4* __restrict__ out)              // (T*B*32) float4
{
    const int gwarp = (blockIdx.x * blockDim.x + threadIdx.x) >> 5;
    const int lane  = threadIdx.x & 31;
    const int row0  = gwarp * 2;                 // first row of the pair
    if (row0 >= TOTAL_ROWS) return;

    const int t  = row0 / B_DIM;                 // same t for both rows
    const int b0 = row0 - t * B_DIM;

    const int ctr0 = row0 * 32 + lane;                         // row0 center
    const int nb0  = (t * T_DIM * B_DIM + b0) * 32 + lane;     // row0 neigh base

    // Issue all 12 big loads up front, streaming (zero reuse).
    const float4 ca = __ldcs(h_center + ctr0);
    const float4 cb = __ldcs(h_center + ctr0 + 32);
    const float4 a0 = __ldcs(h_neigh + nb0 + 0 * B_DIM * 32);
    const float4 b0v= __ldcs(h_neigh + nb0 + 0 * B_DIM * 32 + 32);
    const float4 a1 = __ldcs(h_neigh + nb0 + 1 * B_DIM * 32);
    const float4 b1v= __ldcs(h_neigh + nb0 + 1 * B_DIM * 32 + 32);
    const float4 a2 = __ldcs(h_neigh + nb0 + 2 * B_DIM * 32);
    const float4 b2v= __ldcs(h_neigh + nb0 + 2 * B_DIM * 32 + 32);
    const float4 wh = __ldg(att_w + t * 64 + lane);       // reused: keep cached
    const float4 we = __ldg(att_w + t * 64 + 32 + lane);
    const float bias = __ldg(att_b + t);

    // ---- row 0 partials (score_h folded in) ----
    float pha = ca.x * wh.x + ca.y * wh.y + ca.z * wh.z + ca.w * wh.w;
    float pa0 = a0.x * we.x + a0.y * we.y + a0.z * we.z + a0.w * we.w + pha;
    float pa1 = a1.x * we.x + a1.y * we.y + a1.z * we.z + a1.w * we.w + pha;
    float pa2 = a2.x * we.x + a2.y * we.y + a2.z * we.z + a2.w * we.w + pha;
    float pa3 = ca.x * we.x + ca.y * we.y + ca.z * we.z + ca.w * we.w + pha;
    // ---- row 1 partials ----
    float phb = cb.x * wh.x + cb.y * wh.y + cb.z * wh.z + cb.w * wh.w;
    float pb0 = b0v.x * we.x + b0v.y * we.y + b0v.z * we.z + b0v.w * we.w + phb;
    float pb1 = b1v.x * we.x + b1v.y * we.y + b1v.z * we.z + b1v.w * we.w + phb;
    float pb2 = b2v.x * we.x + b2v.y * we.y + b2v.z * we.z + b2v.w * we.w + phb;
    float pb3 = cb.x * we.x + cb.y * we.y + cb.z * we.z + cb.w * we.w + phb;

    // 8 butterfly reductions, interleaved for ILP.
    #pragma unroll
    for (int off = 16; off > 0; off >>= 1) {
        pa0 += __shfl_xor_sync(0xFFFFFFFFu, pa0, off);
        pa1 += __shfl_xor_sync(0xFFFFFFFFu, pa1, off);
        pa2 += __shfl_xor_sync(0xFFFFFFFFu, pa2, off);
        pa3 += __shfl_xor_sync(0xFFFFFFFFu, pa3, off);
        pb0 += __shfl_xor_sync(0xFFFFFFFFu, pb0, off);
        pb1 += __shfl_xor_sync(0xFFFFFFFFu, pb1, off);
        pb2 += __shfl_xor_sync(0xFFFFFFFFu, pb2, off);
        pb3 += __shfl_xor_sync(0xFFFFFFFFu, pb3, off);
    }

    // ---- row 0 softmax + output ----
    {
        float s0 = pa0 + bias, s1 = pa1 + bias, s2 = pa2 + bias, s3 = pa3 + bias;
        s0 = (s0 >= 0.f) ? s0 : NEG_SLOPE * s0;
        s1 = (s1 >= 0.f) ? s1 : NEG_SLOPE * s1;
        s2 = (s2 >= 0.f) ? s2 : NEG_SLOPE * s2;
        s3 = (s3 >= 0.f) ? s3 : NEG_SLOPE * s3;
        float m = fmaxf(fmaxf(s0, s1), fmaxf(s2, s3));
        float e0 = __expf(s0 - m), e1 = __expf(s1 - m);
        float e2 = __expf(s2 - m), e3 = __expf(s3 - m);
        float inv = __fdividef(1.0f, e0 + e1 + e2 + e3);
        float w0 = e0 * inv, w1 = e1 * inv, w2 = e2 * inv, w3 = e3 * inv;
        float4 o;
        o.x = w0 * a0.x + w1 * a1.x + w2 * a2.x + w3 * ca.x;
        o.y = w0 * a0.y + w1 * a1.y + w2 * a2.y + w3 * ca.y;
        o.z = w0 * a0.z + w1 * a1.z + w2 * a2.z + w3 * ca.z;
        o.w = w0 * a0.w + w1 * a1.w + w2 * a2.w + w3 * ca.w;
        __stcs(out + ctr0, o);
    }
    // ---- row 1 softmax + output ----
    {
        float s0 = pb0 + bias, s1 = pb1 + bias, s2 = pb2 + bias, s3 = pb3 + bias;
        s0 = (s0 >= 0.f) ? s0 : NEG_SLOPE * s0;
        s1 = (s1 >= 0.f) ? s1 : NEG_SLOPE * s1;
        s2 = (s2 >= 0.f) ? s2 : NEG_SLOPE * s2;
        s3 = (s3 >= 0.f) ? s3 : NEG_SLOPE * s3;
        float m = fmaxf(fmaxf(s0, s1), fmaxf(s2, s3));
        float e0 = __expf(s0 - m), e1 = __expf(s1 - m);
        float e2 = __expf(s2 - m), e3 = __expf(s3 - m);
        float inv = __fdividef(1.0f, e0 + e1 + e2 + e3);
        float w0 = e0 * inv, w1 = e1 * inv, w2 = e2 * inv, w3 = e3 * inv;
        float4 o;
        o.x = w0 * b0v.x + w1 * b1v.x + w2 * b2v.x + w3 * cb.x;
        o.y = w0 * b0v.y + w1 * b1v.y + w2 * b2v.y + w3 * cb.y;
        o.z = w0 * b0v.z + w1 * b1v.z + w2 * b2v.z + w3 * cb.z;
        o.w = w0 * b0v.w + w1 * b1v.w + w2 * b2v.w + w3 * cb.w;
        __stcs(out + ctr0 + 32, o);
    }
}

extern "C" void kernel_launch(void* const* d_in, const int* in_sizes, int n_in,
                              void* d_out, int out_size) {
    const float4* h_center = (const float4*)d_in[0];
    const float4* h_neigh  = (const float4*)d_in[1];
    const float4* att_w    = (const float4*)d_in[2];
    const float*  att_b    = (const float*)d_in[3];
    float4* out = (float4*)d_out;

    const int total_pairs = TOTAL_ROWS / 2;             // 150000 warps
    const int threads = 512;                            // 16 warps/block
    const int blocks = (total_pairs * 32 + threads - 1) / threads;  // 9375

    attconv_kernel<<<blocks, threads>>>(h_center, h_neigh, att_w, att_b, out);
}

// round 13
// speedup vs baseline: 1.0340x; 1.0097x over previous
#include <cuda_runtime.h>

#define T_DIM 3
#define B_DIM 100000
#define D_DIM 128
#define NEG_SLOPE 0.01f
#define TOTAL_ROWS (T_DIM * B_DIM)

// 256-bit (v8.f32) streaming load/store helpers — sm_100+ LDG.E.256 path.
__device__ __forceinline__ void ldcs256(const float* __restrict__ p, float r[8]) {
    asm volatile("ld.global.cs.v8.f32 {%0,%1,%2,%3,%4,%5,%6,%7}, [%8];"
                 : "=f"(r[0]), "=f"(r[1]), "=f"(r[2]), "=f"(r[3]),
                   "=f"(r[4]), "=f"(r[5]), "=f"(r[6]), "=f"(r[7])
                 : "l"(p));
}
__device__ __forceinline__ void ldg256(const float* __restrict__ p, float r[8]) {
    asm volatile("ld.global.nc.v8.f32 {%0,%1,%2,%3,%4,%5,%6,%7}, [%8];"
                 : "=f"(r[0]), "=f"(r[1]), "=f"(r[2]), "=f"(r[3]),
                   "=f"(r[4]), "=f"(r[5]), "=f"(r[6]), "=f"(r[7])
                 : "l"(p));
}
__device__ __forceinline__ void stcs256(float* __restrict__ p, const float r[8]) {
    asm volatile("st.global.cs.v8.f32 [%0], {%1,%2,%3,%4,%5,%6,%7,%8};"
                 :: "l"(p),
                    "f"(r[0]), "f"(r[1]), "f"(r[2]), "f"(r[3]),
                    "f"(r[4]), "f"(r[5]), "f"(r[6]), "f"(r[7])
                 : "memory");
}

// One warp per PAIR of consecutive (t,b) rows; each lane owns 8 consecutive
// floats (256-bit). Lanes 0-15 cover row0, lanes 16-31 cover row1. Each big
// stream is ONE v8 load per lane (1KB contiguous per warp instruction).
// Dot-product reduction is a 4-stage butterfly within each 16-lane half.
__global__ __launch_bounds__(512, 2)
void attconv_kernel(const float* __restrict__ h_center,   // (T*B*128)
                    const float* __restrict__ h_neigh,    // (T*T*B*128)
                    const float* __restrict__ att_w,      // (T*256)
                    const float* __restrict__ att_b,      // (T)
                    float* __restrict__ out)              // (T*B*128)
{
    const int gwarp = (blockIdx.x * blockDim.x + threadIdx.x) >> 5;
    const int lane  = threadIdx.x & 31;
    const int row0  = gwarp * 2;                 // first row of the pair
    if (row0 >= TOTAL_ROWS) return;

    const int t  = row0 / B_DIM;                 // same t for both rows
    const int b0 = row0 - t * B_DIM;
    const int hl = lane & 15;                    // position within the row

    // Float offsets: lane*8 spans the 256-float (2-row) pair block.
    const long ctr_off = (long)row0 * 128 + lane * 8;
    const long nb_base = ((long)(t * T_DIM) * B_DIM + b0) * 128 + lane * 8;
    const long nstride = (long)B_DIM * 128;

    // 4 big streaming loads (1KB/warp each) + 2 cached weight loads.
    float c[8], v0[8], v1[8], v2[8], wh[8], we[8];
    ldcs256(h_center + ctr_off, c);
    ldcs256(h_neigh + nb_base + 0 * nstride, v0);
    ldcs256(h_neigh + nb_base + 1 * nstride, v1);
    ldcs256(h_neigh + nb_base + 2 * nstride, v2);
    ldg256(att_w + t * 256 + hl * 8, wh);        // w_h chunk for this lane
    ldg256(att_w + t * 256 + 128 + hl * 8, we);  // w_e chunk for this lane
    const float bias = __ldg(att_b + t);

    // Per-lane partials over this lane's 8 floats; score_h folded in.
    float ph = 0.f, p0 = 0.f, p1 = 0.f, p2 = 0.f, p3 = 0.f;
    #pragma unroll
    for (int i = 0; i < 8; i++) {
        ph += c[i] * wh[i];
        p0 += v0[i] * we[i];
        p1 += v1[i] * we[i];
        p2 += v2[i] * we[i];
        p3 += c[i] * we[i];
    }
    p0 += ph; p1 += ph; p2 += ph; p3 += ph;

    // Butterfly within each 16-lane half (off=1,2,4,8 never crosses halves).
    #pragma unroll
    for (int off = 8; off > 0; off >>= 1) {
        p0 += __shfl_xor_sync(0xFFFFFFFFu, p0, off);
        p1 += __shfl_xor_sync(0xFFFFFFFFu, p1, off);
        p2 += __shfl_xor_sync(0xFFFFFFFFu, p2, off);
        p3 += __shfl_xor_sync(0xFFFFFFFFu, p3, off);
    }

    // Each half now holds its own row's 4 scores. Softmax per half.
    float s0 = p0 + bias, s1 = p1 + bias, s2 = p2 + bias, s3 = p3 + bias;
    s0 = (s0 >= 0.f) ? s0 : NEG_SLOPE * s0;
    s1 = (s1 >= 0.f) ? s1 : NEG_SLOPE * s1;
    s2 = (s2 >= 0.f) ? s2 : NEG_SLOPE * s2;
    s3 = (s3 >= 0.f) ? s3 : NEG_SLOPE * s3;
    float m = fmaxf(fmaxf(s0, s1), fmaxf(s2, s3));
    float e0 = __expf(s0 - m), e1 = __expf(s1 - m);
    float e2 = __expf(s2 - m), e3 = __expf(s3 - m);
    float inv = __fdividef(1.0f, e0 + e1 + e2 + e3);
    float w0 = e0 * inv, w1 = e1 * inv, w2 = e2 * inv, w3 = e3 * inv;

    // Weighted sum over this lane's 8 floats; one 256-bit store.
    float o[8];
    #pragma unroll
    for (int i = 0; i < 8; i++)
        o[i] = w0 * v0[i] + w1 * v1[i] + w2 * v2[i] + w3 * c[i];
    stcs256(out + ctr_off, o);
}

extern "C" void kernel_launch(void* const* d_in, const int* in_sizes, int n_in,
                              void* d_out, int out_size) {
    const float* h_center = (const float*)d_in[0];
    const float* h_neigh  = (const float*)d_in[1];
    const float* att_w    = (const float*)d_in[2];
    const float* att_b    = (const float*)d_in[3];
    float* out = (float*)d_out;

    const int total_pairs = TOTAL_ROWS / 2;             // 150000 warps
    const int threads = 512;                            // 16 warps/block
    const int blocks = (total_pairs * 32 + threads - 1) / threads;  // 9375

    attconv_kernel<<<blocks, threads>>>(h_center, h_neigh, att_w, att_b, out);
}